// round 3
// baseline (speedup 1.0000x reference)
#include <cuda_runtime.h>
#include <math.h>

#define DIM      768
#define HEADS    12
#define HD       64
#define HIDDEN   3072
#define SEQ      577
#define BATCH    64
#define NTOK     (BATCH*SEQ)  // 36928
#define QKVD     (3*DIM)      // 2304

// ---------------- single scratch arena (overlaid buffers) ----------------
// layout (floats):
//   [0,            NTOK*DIM)              h    : LN1 out -> attn out -> LN2 out
//   [NTOK*DIM,     2*NTOK*DIM)            x2   : post-attention residual
//   [2*NTOK*DIM,   2*NTOK*DIM + max(...)) qkv (alive steps 2-3) / m (alive steps 6-7)
#define ARENA_FLOATS ((size_t)NTOK * DIM * 2 + (size_t)NTOK * HIDDEN)
__device__ float g_arena[ARENA_FLOATS];

// ---------------- LayerNorm: one block per token, 768 = 256*3 ----------------
__global__ __launch_bounds__(256) void ln_kernel(
    const float* __restrict__ x, const float* __restrict__ g,
    const float* __restrict__ b, float* __restrict__ out)
{
    const size_t t = blockIdx.x;
    const float* xr = x + t * DIM;
    const int tid = threadIdx.x;

    float v0 = xr[tid], v1 = xr[tid + 256], v2 = xr[tid + 512];
    float s  = v0 + v1 + v2;
    float ss = v0*v0 + v1*v1 + v2*v2;

    __shared__ float red[16];
    __shared__ float stat[2];
    #pragma unroll
    for (int o = 16; o; o >>= 1) {
        s  += __shfl_xor_sync(0xffffffffu, s,  o);
        ss += __shfl_xor_sync(0xffffffffu, ss, o);
    }
    if ((tid & 31) == 0) { red[tid >> 5] = s; red[(tid >> 5) + 8] = ss; }
    __syncthreads();
    if (tid == 0) {
        float a = 0.f, c = 0.f;
        #pragma unroll
        for (int i = 0; i < 8; i++) { a += red[i]; c += red[i + 8]; }
        float mu = a * (1.0f / DIM);
        float var = c * (1.0f / DIM) - mu * mu;
        stat[0] = mu;
        stat[1] = rsqrtf(var + 1e-5f);
    }
    __syncthreads();
    const float mu = stat[0], inv = stat[1];
    float* orow = out + t * DIM;
    orow[tid      ] = (v0 - mu) * inv * g[tid      ] + b[tid      ];
    orow[tid + 256] = (v1 - mu) * inv * g[tid + 256] + b[tid + 256];
    orow[tid + 512] = (v2 - mu) * inv * g[tid + 512] + b[tid + 512];
}

// ---------------- SGEMM 128x128x16, double-buffered, 256 thr, 8x8/thread ----
// A [M,K] rm, B [K,N] rm, C [M,N]. Requires K%16==0, N%128==0.
template<bool BIAS, bool GELU, bool RES>
__global__ __launch_bounds__(256) void sgemm_kernel(
    const float* __restrict__ A, const float* __restrict__ B,
    const float* __restrict__ bias, const float* __restrict__ res,
    float* __restrict__ C, int M, int N, int K)
{
    __shared__ float As[2][16][128];
    __shared__ float Bs[2][16][128];

    const int tid = threadIdx.x;
    const int tx = tid & 15, ty = tid >> 4;
    const int row0 = blockIdx.y * 128, col0 = blockIdx.x * 128;

    // A tile 128x16: each thread 2 float4 (cols acol, acol+... pattern below)
    const int arow = tid >> 1;            // 0..127
    const int acol = (tid & 1) * 8;       // 0 or 8
    // B tile 16x128: rows brow, brow+8; 4 cols each
    const int brow = tid >> 5;            // 0..7
    const int bcol = (tid & 31) * 4;

    const int gar = row0 + arow;
    const bool aval = (gar < M);
    const float* Aptr = A + (size_t)gar * K + acol;
    const float* Bptr = B + (size_t)brow * N + col0 + bcol;
    const size_t bstep8 = (size_t)8 * N;

    float acc[8][8];
    #pragma unroll
    for (int i = 0; i < 8; i++)
        #pragma unroll
        for (int j = 0; j < 8; j++) acc[i][j] = 0.f;

    const int NT = K / 16;

    // ---- preload tile 0 into buffer 0 ----
    {
        float4 a0 = make_float4(0,0,0,0), a1 = make_float4(0,0,0,0);
        if (aval) {
            a0 = *reinterpret_cast<const float4*>(Aptr);
            a1 = *reinterpret_cast<const float4*>(Aptr + 4);
        }
        As[0][acol+0][arow]=a0.x; As[0][acol+1][arow]=a0.y;
        As[0][acol+2][arow]=a0.z; As[0][acol+3][arow]=a0.w;
        As[0][acol+4][arow]=a1.x; As[0][acol+5][arow]=a1.y;
        As[0][acol+6][arow]=a1.z; As[0][acol+7][arow]=a1.w;
        float4 b0 = *reinterpret_cast<const float4*>(Bptr);
        float4 b1 = *reinterpret_cast<const float4*>(Bptr + bstep8);
        *reinterpret_cast<float4*>(&Bs[0][brow    ][bcol]) = b0;
        *reinterpret_cast<float4*>(&Bs[0][brow + 8][bcol]) = b1;
    }
    __syncthreads();

    int buf = 0;
    for (int t = 0; t < NT; t++) {
        float4 a0, a1, b0, b1;
        const bool more = (t + 1 < NT);
        if (more) {
            const int k0 = (t + 1) * 16;
            a0 = make_float4(0,0,0,0); a1 = make_float4(0,0,0,0);
            if (aval) {
                a0 = *reinterpret_cast<const float4*>(Aptr + k0);
                a1 = *reinterpret_cast<const float4*>(Aptr + k0 + 4);
            }
            b0 = *reinterpret_cast<const float4*>(Bptr + (size_t)k0 * N);
            b1 = *reinterpret_cast<const float4*>(Bptr + (size_t)k0 * N + bstep8);
        }

        #pragma unroll
        for (int k = 0; k < 16; k++) {
            float4 ra0 = *reinterpret_cast<const float4*>(&As[buf][k][ty * 8]);
            float4 ra1 = *reinterpret_cast<const float4*>(&As[buf][k][ty * 8 + 4]);
            float4 rb0 = *reinterpret_cast<const float4*>(&Bs[buf][k][tx * 8]);
            float4 rb1 = *reinterpret_cast<const float4*>(&Bs[buf][k][tx * 8 + 4]);
            float ra[8] = {ra0.x,ra0.y,ra0.z,ra0.w,ra1.x,ra1.y,ra1.z,ra1.w};
            float rb[8] = {rb0.x,rb0.y,rb0.z,rb0.w,rb1.x,rb1.y,rb1.z,rb1.w};
            #pragma unroll
            for (int i = 0; i < 8; i++)
                #pragma unroll
                for (int j = 0; j < 8; j++)
                    acc[i][j] = fmaf(ra[i], rb[j], acc[i][j]);
        }

        if (more) {
            const int nb = buf ^ 1;
            As[nb][acol+0][arow]=a0.x; As[nb][acol+1][arow]=a0.y;
            As[nb][acol+2][arow]=a0.z; As[nb][acol+3][arow]=a0.w;
            As[nb][acol+4][arow]=a1.x; As[nb][acol+5][arow]=a1.y;
            As[nb][acol+6][arow]=a1.z; As[nb][acol+7][arow]=a1.w;
            *reinterpret_cast<float4*>(&Bs[nb][brow    ][bcol]) = b0;
            *reinterpret_cast<float4*>(&Bs[nb][brow + 8][bcol]) = b1;
            __syncthreads();
            buf = nb;
        }
    }

    #pragma unroll
    for (int i = 0; i < 8; i++) {
        const int r = row0 + ty * 8 + i;
        if (r >= M) break;
        #pragma unroll
        for (int j = 0; j < 8; j++) {
            const int c = col0 + tx * 8 + j;
            float v = acc[i][j];
            if (BIAS) v += bias[c];
            if (GELU) v = 0.5f * v * (1.0f + erff(v * 0.70710678118654752f));
            if (RES)  v += res[(size_t)r * N + c];
            C[(size_t)r * N + c] = v;
        }
    }
}

// ---------------- Fused flash attention ----------------
// One block per (q-tile of 64, b*h). 256 threads, thread (tx,ty) owns a
// 4x4 patch. Online softmax in registers; P staged through the K smem buffer.
#define FA_SMEM (3 * 64 * 68 * 4)

__global__ __launch_bounds__(256) void fattn_kernel(
    const float* __restrict__ qkv, float* __restrict__ O)
{
    extern __shared__ float sm[];
    float (*Qs)[68] = reinterpret_cast<float(*)[68]>(sm);               // [d][n]
    float (*KP)[68] = reinterpret_cast<float(*)[68]>(sm + 64 * 68);     // K:[d][m] then P:[n][k]
    float (*Vs)[68] = reinterpret_cast<float(*)[68]>(sm + 2 * 64 * 68); // [k][d]

    const int bh = blockIdx.y;
    const int b = bh / HEADS, h = bh % HEADS;
    const int n0 = blockIdx.x * 64;
    const float* qb = qkv + (size_t)b * SEQ * QKVD + h * HD;
    const float* kb = qb + DIM;
    const float* vb = qb + 2 * DIM;

    const int tid = threadIdx.x;
    const int lr = tid >> 2;          // 0..63
    const int lc = (tid & 3) * 16;    // 0,16,32,48
    const int tx = tid & 15, ty = tid >> 4;

    // Q tile, transposed: Qs[d][n]; OOB rows -> 0
    {
        const int n = n0 + lr;
        const float4* src = (n < SEQ)
            ? reinterpret_cast<const float4*>(qb + (size_t)n * QKVD + lc) : nullptr;
        #pragma unroll
        for (int c4 = 0; c4 < 4; c4++) {
            float4 v = src ? src[c4] : make_float4(0.f,0.f,0.f,0.f);
            const int d = lc + c4 * 4;
            Qs[d][lr]=v.x; Qs[d+1][lr]=v.y; Qs[d+2][lr]=v.z; Qs[d+3][lr]=v.w;
        }
    }

    float acc_o[4][4];
    float row_m[4], row_l[4];
    #pragma unroll
    for (int i = 0; i < 4; i++) {
        row_m[i] = -1e30f; row_l[i] = 0.f;
        #pragma unroll
        for (int j = 0; j < 4; j++) acc_o[i][j] = 0.f;
    }

    for (int k0 = 0; k0 < SEQ; k0 += 64) {
        __syncthreads();  // previous PV (and Q store on iter 0) complete
        {
            const int m = k0 + lr;
            const float4* srck = (m < SEQ)
                ? reinterpret_cast<const float4*>(kb + (size_t)m * QKVD + lc) : nullptr;
            const float4* srcv = (m < SEQ)
                ? reinterpret_cast<const float4*>(vb + (size_t)m * QKVD + lc) : nullptr;
            #pragma unroll
            for (int c4 = 0; c4 < 4; c4++) {
                float4 v = srck ? srck[c4] : make_float4(0.f,0.f,0.f,0.f);
                const int d = lc + c4 * 4;
                KP[d][lr]=v.x; KP[d+1][lr]=v.y; KP[d+2][lr]=v.z; KP[d+3][lr]=v.w;
                float4 w = srcv ? srcv[c4] : make_float4(0.f,0.f,0.f,0.f);
                *reinterpret_cast<float4*>(&Vs[lr][lc + c4 * 4]) = w;
            }
        }
        __syncthreads();

        // S = Q K^T (4x4 per thread)
        float s[4][4];
        #pragma unroll
        for (int i = 0; i < 4; i++)
            #pragma unroll
            for (int j = 0; j < 4; j++) s[i][j] = 0.f;

        #pragma unroll 8
        for (int d = 0; d < 64; d++) {
            float4 ra = *reinterpret_cast<const float4*>(&Qs[d][ty * 4]);
            float4 rb = *reinterpret_cast<const float4*>(&KP[d][tx * 4]);
            float a[4] = {ra.x, ra.y, ra.z, ra.w};
            float bb[4] = {rb.x, rb.y, rb.z, rb.w};
            #pragma unroll
            for (int i = 0; i < 4; i++)
                #pragma unroll
                for (int j = 0; j < 4; j++)
                    s[i][j] = fmaf(a[i], bb[j], s[i][j]);
        }

        #pragma unroll
        for (int i = 0; i < 4; i++)
            #pragma unroll
            for (int j = 0; j < 4; j++) {
                s[i][j] *= 0.125f;
                if (k0 + tx * 4 + j >= SEQ) s[i][j] = -1e30f;
            }

        // online softmax update (row reduction over the 16 tx lanes)
        float f[4];
        #pragma unroll
        for (int i = 0; i < 4; i++) {
            float mt = fmaxf(fmaxf(s[i][0], s[i][1]), fmaxf(s[i][2], s[i][3]));
            #pragma unroll
            for (int o = 1; o < 16; o <<= 1)
                mt = fmaxf(mt, __shfl_xor_sync(0xffffffffu, mt, o, 16));
            const float nm = fmaxf(row_m[i], mt);
            f[i] = __expf(row_m[i] - nm);
            row_m[i] = nm;
            float rs = 0.f;
            #pragma unroll
            for (int j = 0; j < 4; j++) {
                s[i][j] = __expf(s[i][j] - nm);
                rs += s[i][j];
            }
            #pragma unroll
            for (int o = 1; o < 16; o <<= 1)
                rs += __shfl_xor_sync(0xffffffffu, rs, o, 16);
            row_l[i] = row_l[i] * f[i] + rs;
            #pragma unroll
            for (int j = 0; j < 4; j++) acc_o[i][j] *= f[i];
        }

        __syncthreads();  // everyone done reading KP as K
        #pragma unroll
        for (int i = 0; i < 4; i++)
            *reinterpret_cast<float4*>(&KP[ty * 4 + i][tx * 4]) =
                make_float4(s[i][0], s[i][1], s[i][2], s[i][3]);
        __syncthreads();

        // O += P V
        #pragma unroll 4
        for (int k = 0; k < 64; k += 4) {
            float4 pa[4], vv[4];
            #pragma unroll
            for (int i = 0; i < 4; i++)
                pa[i] = *reinterpret_cast<const float4*>(&KP[ty * 4 + i][k]);
            #pragma unroll
            for (int kk = 0; kk < 4; kk++)
                vv[kk] = *reinterpret_cast<const float4*>(&Vs[k + kk][tx * 4]);
            #pragma unroll
            for (int i = 0; i < 4; i++) {
                float p[4] = {pa[i].x, pa[i].y, pa[i].z, pa[i].w};
                #pragma unroll
                for (int kk = 0; kk < 4; kk++) {
                    acc_o[i][0] = fmaf(p[kk], vv[kk].x, acc_o[i][0]);
                    acc_o[i][1] = fmaf(p[kk], vv[kk].y, acc_o[i][1]);
                    acc_o[i][2] = fmaf(p[kk], vv[kk].z, acc_o[i][2]);
                    acc_o[i][3] = fmaf(p[kk], vv[kk].w, acc_o[i][3]);
                }
            }
        }
    }

    #pragma unroll
    for (int i = 0; i < 4; i++) {
        const int n = n0 + ty * 4 + i;
        if (n >= SEQ) continue;
        const float inv = 1.0f / row_l[i];
        float4 r = make_float4(acc_o[i][0]*inv, acc_o[i][1]*inv,
                               acc_o[i][2]*inv, acc_o[i][3]*inv);
        *reinterpret_cast<float4*>(
            O + ((size_t)(b * SEQ + n)) * DIM + h * HD + tx * 4) = r;
    }
}

// ---------------- launch ----------------
extern "C" void kernel_launch(void* const* d_in, const int* in_sizes, int n_in,
                              void* d_out, int out_size)
{
    const float* x     = (const float*)d_in[0];
    const float* ln1_g = (const float*)d_in[1];
    const float* ln1_b = (const float*)d_in[2];
    const float* Wqkv  = (const float*)d_in[3];
    const float* Wproj = (const float*)d_in[4];
    const float* bproj = (const float*)d_in[5];
    const float* ln2_g = (const float*)d_in[6];
    const float* ln2_b = (const float*)d_in[7];
    const float* W1    = (const float*)d_in[8];
    const float* b1    = (const float*)d_in[9];
    const float* W2    = (const float*)d_in[10];
    const float* b2    = (const float*)d_in[11];
    float* out = (float*)d_out;

    void* p_arena;
    cudaGetSymbolAddress(&p_arena, g_arena);
    float* arena = (float*)p_arena;
    float* h_buf = arena;                               // NTOK*DIM
    float* x2buf = arena + (size_t)NTOK * DIM;          // NTOK*DIM
    float* qkvb  = arena + (size_t)NTOK * DIM * 2;      // NTOK*QKVD (overlaid)
    float* mbuf  = qkvb;                                // NTOK*HIDDEN (overlaid)

    cudaFuncSetAttribute(fattn_kernel,
                         cudaFuncAttributeMaxDynamicSharedMemorySize, FA_SMEM);

    const int MT = (NTOK + 127) / 128;  // 289

    // 1. h = LN1(x)
    ln_kernel<<<NTOK, 256>>>(x, ln1_g, ln1_b, h_buf);
    // 2. qkv = h @ Wqkv
    sgemm_kernel<false,false,false><<<dim3(QKVD/128, MT), 256>>>(
        h_buf, Wqkv, nullptr, nullptr, qkvb, NTOK, QKVD, DIM);
    // 3. fused attention -> h_buf (reused; qkv dead afterwards)
    fattn_kernel<<<dim3(10, BATCH*HEADS), 256, FA_SMEM>>>(qkvb, h_buf);
    // 4. x2 = x + O @ Wproj + bproj
    sgemm_kernel<true,false,true><<<dim3(DIM/128, MT), 256>>>(
        h_buf, Wproj, bproj, x, x2buf, NTOK, DIM, DIM);
    // 5. h = LN2(x2)
    ln_kernel<<<NTOK, 256>>>(x2buf, ln2_g, ln2_b, h_buf);
    // 6. m = gelu(h @ W1 + b1)   (m overlays dead qkv)
    sgemm_kernel<true,true,false><<<dim3(HIDDEN/128, MT), 256>>>(
        h_buf, W1, b1, nullptr, mbuf, NTOK, HIDDEN, DIM);
    // 7. out = x2 + m @ W2 + b2
    sgemm_kernel<true,false,true><<<dim3(DIM/128, MT), 256>>>(
        mbuf, W2, b2, x2buf, out, NTOK, DIM, HIDDEN);
}

// round 5
// speedup vs baseline: 1.9915x; 1.9915x over previous
#include <cuda_runtime.h>
#include <math.h>
#include <stdint.h>

#define DIM      768
#define HEADS    12
#define HD       64
#define HIDDEN   3072
#define SEQ      577
#define BATCH    64
#define NTOK     (BATCH*SEQ)  // 36928
#define QKVD     (3*DIM)      // 2304

// ---------------- single scratch arena (overlaid buffers) ----------------
#define ARENA_FLOATS ((size_t)NTOK * DIM * 2 + (size_t)NTOK * HIDDEN)
__device__ float g_arena[ARENA_FLOATS];

// ---------------- helpers ----------------
__device__ __forceinline__ uint32_t smem_u32(const void* p) {
    uint32_t a;
    asm("{ .reg .u64 t; cvta.to.shared.u64 t, %1; cvt.u32.u64 %0, t; }"
        : "=r"(a) : "l"(p));
    return a;
}
// round-to-nearest-even bf16 bits of f
__device__ __forceinline__ uint32_t bf16h(float f) {
    uint32_t u = __float_as_uint(f);
    return (u + 0x7FFFu + ((u >> 16) & 1u)) >> 16;
}
__device__ __forceinline__ float bf16f(uint32_t h) {
    return __uint_as_float(h << 16);
}

#define LDSM4(r0, r1, r2, r3, addr) \
    asm volatile("ldmatrix.sync.aligned.m8n8.x4.shared.b16 {%0,%1,%2,%3}, [%4];" \
                 : "=r"(r0), "=r"(r1), "=r"(r2), "=r"(r3) : "r"(addr))

#define MMA_BF16(d, a, b) \
    asm volatile("mma.sync.aligned.m16n8k16.row.col.f32.bf16.bf16.f32 " \
                 "{%0,%1,%2,%3}, {%4,%5,%6,%7}, {%8,%9}, {%0,%1,%2,%3};" \
                 : "+f"((d)[0]), "+f"((d)[1]), "+f"((d)[2]), "+f"((d)[3]) \
                 : "r"((a)[0]), "r"((a)[1]), "r"((a)[2]), "r"((a)[3]), \
                   "r"((b)[0]), "r"((b)[1]))

// ============ bf16-split tensor-core GEMM: 128x128 tile, K-block 32 ==========
// A [M,K] rm, B [K,N] rm, C [M,N]. K%32==0, N%128==0.
// Each fp32 a = ah+al; smem holds K expanded 3x:
//   A slots per k: [ah, ah, al]   B slots per k: [bh, bl, bh]
// so bf16 mma over 96 slots computes ah*bh + ah*bl + al*bh.
// smem per buffer: A 128 rows x 104(bf16 pitch) , B 128 cols x 104. 2 buffers.
#define PITCHB   208                    // bytes per smem row (104 bf16)
#define TILEB    (128 * PITCHB)         // 26624 bytes
#define BUFB     (2 * TILEB)            // A+B = 53248
#define GEMM_SMEM (2 * BUFB)            // 106496

template<bool BIAS, bool GELU, bool RES>
__global__ __launch_bounds__(256) void tcgemm_kernel(
    const float* __restrict__ A, const float* __restrict__ B,
    const float* __restrict__ bias, const float* __restrict__ res,
    float* __restrict__ C, int M, int N, int K)
{
    extern __shared__ char smem[];
    const uint32_t sb = smem_u32(smem);
    const int tid  = threadIdx.x;
    const int lane = tid & 31;
    const int wid  = tid >> 5;
    const int wr = wid >> 2, wc = wid & 3;        // warp grid 2 x 4
    const int m0w = wr * 64, n0w = wc * 32;       // warp tile 64 x 32

    const int m0 = blockIdx.y * 128, col0 = blockIdx.x * 128;

    // ---- loader indices ----
    const int arow = tid >> 1, aseg = tid & 1;            // A: 2 thr/row, 16 floats each
    const int gar = m0 + arow;
    const bool aval = (gar < M);
    const float* Ap = A + (size_t)gar * K + aseg * 16;
    char* sArow = smem + arow * PITCHB + aseg * 96;       // slot 48*aseg -> byte 96*aseg

    const int bn = tid & 127, bkh = (tid >> 7) * 16;      // B: col bn, k-half bkh
    const float* Bp = B + (size_t)bkh * N + col0 + bn;
    char* sBrow = smem + TILEB + bn * PITCHB + bkh * 6;   // slot 3*bkh -> byte 6*bkh

    float dacc[16][4];
    #pragma unroll
    for (int t = 0; t < 16; t++)
        #pragma unroll
        for (int c = 0; c < 4; c++) dacc[t][c] = 0.f;

    const int NBLK = K >> 5;

    // ---- conversion+store of one k-block into buffer bufo ----
    auto store_tiles = [&](int bufo, const float4 a4[4], const float bl[16]) {
        char* dst = sArow + bufo;
        #pragma unroll
        for (int q = 0; q < 4; q++) {
            const float v[4] = {a4[q].x, a4[q].y, a4[q].z, a4[q].w};
            #pragma unroll
            for (int pp = 0; pp < 2; pp++) {           // pair (k,k+1)
                const float v0 = v[pp*2], v1 = v[pp*2+1];
                const uint32_t h0 = bf16h(v0);
                const uint32_t l0 = bf16h(v0 - bf16f(h0));
                const uint32_t h1 = bf16h(v1);
                const uint32_t l1 = bf16h(v1 - bf16f(h1));
                uint32_t* w = reinterpret_cast<uint32_t*>(dst + (q*2 + pp) * 12);
                w[0] = h0 | (h0 << 16);
                w[1] = l0 | (h1 << 16);
                w[2] = h1 | (l1 << 16);
            }
        }
        char* dstb = sBrow + bufo;
        #pragma unroll
        for (int j = 0; j < 8; j++) {                  // pair (k,k+1)
            const float v0 = bl[2*j], v1 = bl[2*j+1];
            const uint32_t h0 = bf16h(v0);
            const uint32_t l0 = bf16h(v0 - bf16f(h0));
            const uint32_t h1 = bf16h(v1);
            const uint32_t l1 = bf16h(v1 - bf16f(h1));
            uint32_t* w = reinterpret_cast<uint32_t*>(dstb + j * 12);
            w[0] = h0 | (l0 << 16);
            w[1] = h0 | (h1 << 16);
            w[2] = l1 | (h1 << 16);
        }
    };

    // ---- preload block 0 ----
    {
        float4 a4[4]; float bl[16];
        #pragma unroll
        for (int q = 0; q < 4; q++)
            a4[q] = aval ? *reinterpret_cast<const float4*>(Ap + q * 4)
                         : make_float4(0.f, 0.f, 0.f, 0.f);
        #pragma unroll
        for (int i = 0; i < 16; i++) bl[i] = Bp[(size_t)i * N];
        store_tiles(0, a4, bl);
    }
    __syncthreads();

    int buf = 0;
    for (int blk = 0; blk < NBLK; blk++) {
        // prefetch next block into registers
        float4 a4[4]; float bl[16];
        const bool more = (blk + 1 < NBLK);
        if (more) {
            const float* Apn = Ap + (blk + 1) * 32;
            const float* Bpn = Bp + (size_t)(blk + 1) * 32 * N;
            #pragma unroll
            for (int q = 0; q < 4; q++)
                a4[q] = aval ? *reinterpret_cast<const float4*>(Apn + q * 4)
                             : make_float4(0.f, 0.f, 0.f, 0.f);
            #pragma unroll
            for (int i = 0; i < 16; i++) bl[i] = Bpn[(size_t)i * N];
        }

        // ---- compute on buffer `buf`: 6 chunks of 16 bf16 slots ----
        const uint32_t sA = sb + buf * BUFB;
        const uint32_t sBB = sA + TILEB;
        const uint32_t aAddrBase = sA + (uint32_t)(m0w + (lane & 15)) * PITCHB
                                      + ((lane >> 4) * 8) * 2;
        const int g = lane >> 3;
        const uint32_t bAddrBase = sBB + (uint32_t)(n0w + ((g >> 1) * 8) + (lane & 7)) * PITCHB
                                       + ((g & 1) * 8) * 2;
        #pragma unroll
        for (int kc = 0; kc < 6; kc++) {
            uint32_t af[4][4], bf[4][2];
            #pragma unroll
            for (int mi = 0; mi < 4; mi++)
                LDSM4(af[mi][0], af[mi][1], af[mi][2], af[mi][3],
                      aAddrBase + (uint32_t)mi * 16 * PITCHB + kc * 32);
            LDSM4(bf[0][0], bf[0][1], bf[1][0], bf[1][1], bAddrBase + kc * 32);
            LDSM4(bf[2][0], bf[2][1], bf[3][0], bf[3][1],
                  bAddrBase + 16 * PITCHB + kc * 32);
            #pragma unroll
            for (int mi = 0; mi < 4; mi++)
                #pragma unroll
                for (int nt = 0; nt < 4; nt++)
                    MMA_BF16(dacc[mi * 4 + nt], af[mi], bf[nt]);
        }

        if (more) {
            store_tiles((buf ^ 1) * BUFB, a4, bl);
            __syncthreads();
            buf ^= 1;
        }
    }

    // ---- epilogue ----
    #pragma unroll
    for (int mi = 0; mi < 4; mi++) {
        const int r0 = m0 + m0w + mi * 16 + (lane >> 2);
        #pragma unroll
        for (int nt = 0; nt < 4; nt++) {
            const int c = col0 + n0w + nt * 8 + (lane & 3) * 2;
            const float* d = dacc[mi * 4 + nt];
            float b0 = 0.f, b1 = 0.f;
            if (BIAS) { b0 = bias[c]; b1 = bias[c + 1]; }
            #pragma unroll
            for (int half = 0; half < 2; half++) {
                const int r = r0 + half * 8;
                if (r >= M) continue;
                float v0 = d[half * 2 + 0] + b0;
                float v1 = d[half * 2 + 1] + b1;
                if (GELU) {
                    v0 = 0.5f * v0 * (1.0f + erff(v0 * 0.70710678118654752f));
                    v1 = 0.5f * v1 * (1.0f + erff(v1 * 0.70710678118654752f));
                }
                if (RES) {
                    const float2 rv = *reinterpret_cast<const float2*>(
                        res + (size_t)r * N + c);
                    v0 += rv.x; v1 += rv.y;
                }
                *reinterpret_cast<float2*>(C + (size_t)r * N + c) =
                    make_float2(v0, v1);
            }
        }
    }
}

// ---------------- LayerNorm: one block per token, 768 = 256*3 ----------------
__global__ __launch_bounds__(256) void ln_kernel(
    const float* __restrict__ x, const float* __restrict__ g,
    const float* __restrict__ b, float* __restrict__ out)
{
    const size_t t = blockIdx.x;
    const float* xr = x + t * DIM;
    const int tid = threadIdx.x;

    float v0 = xr[tid], v1 = xr[tid + 256], v2 = xr[tid + 512];
    float s  = v0 + v1 + v2;
    float ss = v0*v0 + v1*v1 + v2*v2;

    __shared__ float red[16];
    __shared__ float stat[2];
    #pragma unroll
    for (int o = 16; o; o >>= 1) {
        s  += __shfl_xor_sync(0xffffffffu, s,  o);
        ss += __shfl_xor_sync(0xffffffffu, ss, o);
    }
    if ((tid & 31) == 0) { red[tid >> 5] = s; red[(tid >> 5) + 8] = ss; }
    __syncthreads();
    if (tid == 0) {
        float a = 0.f, c = 0.f;
        #pragma unroll
        for (int i = 0; i < 8; i++) { a += red[i]; c += red[i + 8]; }
        float mu = a * (1.0f / DIM);
        float var = c * (1.0f / DIM) - mu * mu;
        stat[0] = mu;
        stat[1] = rsqrtf(var + 1e-5f);
    }
    __syncthreads();
    const float mu = stat[0], inv = stat[1];
    float* orow = out + t * DIM;
    orow[tid      ] = (v0 - mu) * inv * g[tid      ] + b[tid      ];
    orow[tid + 256] = (v1 - mu) * inv * g[tid + 256] + b[tid + 256];
    orow[tid + 512] = (v2 - mu) * inv * g[tid + 512] + b[tid + 512];
}

// ---------------- Fused flash attention (SIMT) ----------------
#define FA_SMEM (3 * 64 * 68 * 4)

__global__ __launch_bounds__(256) void fattn_kernel(
    const float* __restrict__ qkv, float* __restrict__ O)
{
    extern __shared__ float sm[];
    float (*Qs)[68] = reinterpret_cast<float(*)[68]>(sm);               // [d][n]
    float (*KP)[68] = reinterpret_cast<float(*)[68]>(sm + 64 * 68);     // K:[d][m] then P:[n][k]
    float (*Vs)[68] = reinterpret_cast<float(*)[68]>(sm + 2 * 64 * 68); // [k][d]

    const int bh = blockIdx.y;
    const int b = bh / HEADS, h = bh % HEADS;
    const int n0 = blockIdx.x * 64;
    const float* qb = qkv + (size_t)b * SEQ * QKVD + h * HD;
    const float* kb = qb + DIM;
    const float* vb = qb + 2 * DIM;

    const int tid = threadIdx.x;
    const int lr = tid >> 2;          // 0..63
    const int lc = (tid & 3) * 16;    // 0,16,32,48
    const int tx = tid & 15, ty = tid >> 4;

    {
        const int n = n0 + lr;
        const float4* src = (n < SEQ)
            ? reinterpret_cast<const float4*>(qb + (size_t)n * QKVD + lc) : nullptr;
        #pragma unroll
        for (int c4 = 0; c4 < 4; c4++) {
            float4 v = src ? src[c4] : make_float4(0.f,0.f,0.f,0.f);
            const int d = lc + c4 * 4;
            Qs[d][lr]=v.x; Qs[d+1][lr]=v.y; Qs[d+2][lr]=v.z; Qs[d+3][lr]=v.w;
        }
    }

    float acc_o[4][4];
    float row_m[4], row_l[4];
    #pragma unroll
    for (int i = 0; i < 4; i++) {
        row_m[i] = -1e30f; row_l[i] = 0.f;
        #pragma unroll
        for (int j = 0; j < 4; j++) acc_o[i][j] = 0.f;
    }

    for (int k0 = 0; k0 < SEQ; k0 += 64) {
        __syncthreads();
        {
            const int m = k0 + lr;
            const float4* srck = (m < SEQ)
                ? reinterpret_cast<const float4*>(kb + (size_t)m * QKVD + lc) : nullptr;
            const float4* srcv = (m < SEQ)
                ? reinterpret_cast<const float4*>(vb + (size_t)m * QKVD + lc) : nullptr;
            #pragma unroll
            for (int c4 = 0; c4 < 4; c4++) {
                float4 v = srck ? srck[c4] : make_float4(0.f,0.f,0.f,0.f);
                const int d = lc + c4 * 4;
                KP[d][lr]=v.x; KP[d+1][lr]=v.y; KP[d+2][lr]=v.z; KP[d+3][lr]=v.w;
                float4 w = srcv ? srcv[c4] : make_float4(0.f,0.f,0.f,0.f);
                *reinterpret_cast<float4*>(&Vs[lr][lc + c4 * 4]) = w;
            }
        }
        __syncthreads();

        float s[4][4];
        #pragma unroll
        for (int i = 0; i < 4; i++)
            #pragma unroll
            for (int j = 0; j < 4; j++) s[i][j] = 0.f;

        #pragma unroll 8
        for (int d = 0; d < 64; d++) {
            float4 ra = *reinterpret_cast<const float4*>(&Qs[d][ty * 4]);
            float4 rb = *reinterpret_cast<const float4*>(&KP[d][tx * 4]);
            float a[4] = {ra.x, ra.y, ra.z, ra.w};
            float bb[4] = {rb.x, rb.y, rb.z, rb.w};
            #pragma unroll
            for (int i = 0; i < 4; i++)
                #pragma unroll
                for (int j = 0; j < 4; j++)
                    s[i][j] = fmaf(a[i], bb[j], s[i][j]);
        }

        #pragma unroll
        for (int i = 0; i < 4; i++)
            #pragma unroll
            for (int j = 0; j < 4; j++) {
                s[i][j] *= 0.125f;
                if (k0 + tx * 4 + j >= SEQ) s[i][j] = -1e30f;
            }

        float f[4];
        #pragma unroll
        for (int i = 0; i < 4; i++) {
            float mt = fmaxf(fmaxf(s[i][0], s[i][1]), fmaxf(s[i][2], s[i][3]));
            #pragma unroll
            for (int o = 1; o < 16; o <<= 1)
                mt = fmaxf(mt, __shfl_xor_sync(0xffffffffu, mt, o, 16));
            const float nm = fmaxf(row_m[i], mt);
            f[i] = __expf(row_m[i] - nm);
            row_m[i] = nm;
            float rs = 0.f;
            #pragma unroll
            for (int j = 0; j < 4; j++) {
                s[i][j] = __expf(s[i][j] - nm);
                rs += s[i][j];
            }
            #pragma unroll
            for (int o = 1; o < 16; o <<= 1)
                rs += __shfl_xor_sync(0xffffffffu, rs, o, 16);
            row_l[i] = row_l[i] * f[i] + rs;
            #pragma unroll
            for (int j = 0; j < 4; j++) acc_o[i][j] *= f[i];
        }

        __syncthreads();
        #pragma unroll
        for (int i = 0; i < 4; i++)
            *reinterpret_cast<float4*>(&KP[ty * 4 + i][tx * 4]) =
                make_float4(s[i][0], s[i][1], s[i][2], s[i][3]);
        __syncthreads();

        #pragma unroll 4
        for (int k = 0; k < 64; k += 4) {
            float4 pa[4], vv[4];
            #pragma unroll
            for (int i = 0; i < 4; i++)
                pa[i] = *reinterpret_cast<const float4*>(&KP[ty * 4 + i][k]);
            #pragma unroll
            for (int kk = 0; kk < 4; kk++)
                vv[kk] = *reinterpret_cast<const float4*>(&Vs[k + kk][tx * 4]);
            #pragma unroll
            for (int i = 0; i < 4; i++) {
                float p[4] = {pa[i].x, pa[i].y, pa[i].z, pa[i].w};
                #pragma unroll
                for (int kk = 0; kk < 4; kk++) {
                    acc_o[i][0] = fmaf(p[kk], vv[kk].x, acc_o[i][0]);
                    acc_o[i][1] = fmaf(p[kk], vv[kk].y, acc_o[i][1]);
                    acc_o[i][2] = fmaf(p[kk], vv[kk].z, acc_o[i][2]);
                    acc_o[i][3] = fmaf(p[kk], vv[kk].w, acc_o[i][3]);
                }
            }
        }
    }

    #pragma unroll
    for (int i = 0; i < 4; i++) {
        const int n = n0 + ty * 4 + i;
        if (n >= SEQ) continue;
        const float inv = 1.0f / row_l[i];
        float4 r = make_float4(acc_o[i][0]*inv, acc_o[i][1]*inv,
                               acc_o[i][2]*inv, acc_o[i][3]*inv);
        *reinterpret_cast<float4*>(
            O + ((size_t)(b * SEQ + n)) * DIM + h * HD + tx * 4) = r;
    }
}

// ---------------- launch ----------------
extern "C" void kernel_launch(void* const* d_in, const int* in_sizes, int n_in,
                              void* d_out, int out_size)
{
    const float* x     = (const float*)d_in[0];
    const float* ln1_g = (const float*)d_in[1];
    const float* ln1_b = (const float*)d_in[2];
    const float* Wqkv  = (const float*)d_in[3];
    const float* Wproj = (const float*)d_in[4];
    const float* bproj = (const float*)d_in[5];
    const float* ln2_g = (const float*)d_in[6];
    const float* ln2_b = (const float*)d_in[7];
    const float* W1    = (const float*)d_in[8];
    const float* b1    = (const float*)d_in[9];
    const float* W2    = (const float*)d_in[10];
    const float* b2    = (const float*)d_in[11];
    float* out = (float*)d_out;

    void* p_arena;
    cudaGetSymbolAddress(&p_arena, g_arena);
    float* arena = (float*)p_arena;
    float* h_buf = arena;                               // NTOK*DIM
    float* x2buf = arena + (size_t)NTOK * DIM;          // NTOK*DIM
    float* qkvb  = arena + (size_t)NTOK * DIM * 2;      // NTOK*QKVD (overlaid)
    float* mbuf  = qkvb;                                // NTOK*HIDDEN (overlaid)

    cudaFuncSetAttribute(fattn_kernel,
                         cudaFuncAttributeMaxDynamicSharedMemorySize, FA_SMEM);
    cudaFuncSetAttribute(tcgemm_kernel<false,false,false>,
                         cudaFuncAttributeMaxDynamicSharedMemorySize, GEMM_SMEM);
    cudaFuncSetAttribute(tcgemm_kernel<true,false,true>,
                         cudaFuncAttributeMaxDynamicSharedMemorySize, GEMM_SMEM);
    cudaFuncSetAttribute(tcgemm_kernel<true,true,false>,
                         cudaFuncAttributeMaxDynamicSharedMemorySize, GEMM_SMEM);

    const int MT = (NTOK + 127) / 128;  // 289

    // 1. h = LN1(x)
    ln_kernel<<<NTOK, 256>>>(x, ln1_g, ln1_b, h_buf);
    // 2. qkv = h @ Wqkv
    tcgemm_kernel<false,false,false><<<dim3(QKVD/128, MT), 256, GEMM_SMEM>>>(
        h_buf, Wqkv, nullptr, nullptr, qkvb, NTOK, QKVD, DIM);
    // 3. fused attention -> h_buf (reused; qkv dead afterwards)
    fattn_kernel<<<dim3(10, BATCH*HEADS), 256, FA_SMEM>>>(qkvb, h_buf);
    // 4. x2 = x + O @ Wproj + bproj
    tcgemm_kernel<true,false,true><<<dim3(DIM/128, MT), 256, GEMM_SMEM>>>(
        h_buf, Wproj, bproj, x, x2buf, NTOK, DIM, DIM);
    // 5. h = LN2(x2)
    ln_kernel<<<NTOK, 256>>>(x2buf, ln2_g, ln2_b, h_buf);
    // 6. m = gelu(h @ W1 + b1)   (m overlays dead qkv)
    tcgemm_kernel<true,true,false><<<dim3(HIDDEN/128, MT), 256, GEMM_SMEM>>>(
        h_buf, W1, b1, nullptr, mbuf, NTOK, HIDDEN, DIM);
    // 7. out = x2 + m @ W2 + b2
    tcgemm_kernel<true,false,true><<<dim3(DIM/128, MT), 256, GEMM_SMEM>>>(
        mbuf, W2, b2, x2buf, out, NTOK, DIM, HIDDEN);
}